// round 11
// baseline (speedup 1.0000x reference)
#include <cuda_runtime.h>
#include <cuda_bf16.h>
#include <cstdint>

#define SLOT_ELEMS 45154304ull
#define OFF64 0ull
#define OFF32 35684352ull
#define OFF16 0ull
#define OFF8  4000000ull

__device__ __align__(16) signed char g_acti[6][SLOT_ELEMS];   // int8 activations (value = int/64)
__device__ __align__(16) float       g_scratch[33554432];     // fp32 pre-BN [pixel][256]
__device__ __align__(16) uint2       g_wf[73728];             // [tap][kc8][nb][lane] s8 B fragments
__device__ double g_sum[256];
__device__ double g_sqsum[256];
__device__ float  g_mu[256];
__device__ float  g_rstd[256];
__device__ float  g_feat[32 * 256];

__device__ __forceinline__ unsigned su32(const void* p) {
    return (unsigned)__cvta_generic_to_shared(p);
}

#define IMMA_(c, a, b)                                                          \
    asm volatile("mma.sync.aligned.m16n8k32.row.col.s32.s8.s8.s32 "             \
                 "{%0,%1,%2,%3},{%4,%5,%6,%7},{%8,%9},{%0,%1,%2,%3};\n"         \
                 : "+r"(c[0]), "+r"(c[1]), "+r"(c[2]), "+r"(c[3])               \
                 : "r"(a[0]), "r"(a[1]), "r"(a[2]), "r"(a[3]),                  \
                   "r"(b.x), "r"(b.y))

// conv_w (OIHW fp32, int/64) -> s8 fragments g_wf[((tap*8+kc)*32+nb)*32+lane]
// b0 = w[co=nb*8+g][k=32kc+4qd..+3], b1 = w[..][32kc+16+4qd..+3]
__global__ void k_prep_w(const float* __restrict__ cw) {
    int idx = blockIdx.x * 256 + threadIdx.x;
    if (idx < 256) { g_sum[idx] = 0.0; g_sqsum[idx] = 0.0; }
    if (idx >= 73728) return;
    int lane = idx & 31, nb = (idx >> 5) & 31, kc = (idx >> 10) & 7, tap = idx >> 13;
    int g = lane >> 2, qd = lane & 3;
    int co = nb * 8 + g, k0 = kc * 32 + 4 * qd;
    unsigned b0 = 0, b1 = 0;
#pragma unroll
    for (int j = 0; j < 4; j++) {
        int v0 = (int)rintf(cw[(co * 256 + k0 + j) * 9 + tap] * 64.f);
        int v1 = (int)rintf(cw[(co * 256 + k0 + 16 + j) * 9 + tap] * 64.f);
        b0 |= ((unsigned)(unsigned char)(signed char)v0) << (8 * j);
        b1 |= ((unsigned)(unsigned char)(signed char)v1) << (8 * j);
    }
    uint2 v; v.x = b0; v.y = b1;
    g_wf[idx] = v;
}

// x (32,3,64,64) fp32 -> q=trunc(x/64) int8, pad ch->256, padded NHWC slot0
__global__ void k_prep_in(const float* __restrict__ x) {
    long long e = (long long)blockIdx.x * 256 + threadIdx.x;
    if (e >= 35684352ll) return;
    int c = (int)(e & 255);
    long long r = e >> 8;
    int px = (int)(r % 66); r /= 66;
    int py = (int)(r % 66); int n = (int)(r / 66);
    signed char q = 0;
    if (py >= 1 && py <= 64 && px >= 1 && px <= 64 && c < 3) {
        float xv = x[(((long long)n * 3 + c) * 64 + (py - 1)) * 64 + (px - 1)];
        q = (signed char)(int)truncf(xv * 0.015625f);
    }
    g_acti[0][e] = q;
}

// ---------------------------------------------------------------------------
// Big conv (t<9): CTA 512 thr, 16 warps (8M x 2N), warp M32 x N64.
// Tile M256 x N128, K=2304 as 8 stages of 32 channels, triple-buffered.
// ---------------------------------------------------------------------------
__global__ void __launch_bounds__(512, 1) k_conv(
    int sPrev, int s1, int s2, int s3, int s4, int nhist,
    unsigned long long off, int lw,
    const float* __restrict__ alpha, int t)
{
    extern __shared__ __align__(16) char dynsmem[];
    __shared__ float s_sum[128], s_sq[128];

    const int tid = threadIdx.x, warp = tid >> 5, lane = tid & 31;
    const int g = lane >> 2, qd = lane & 3;
    const int mw = warp >> 1, nw = warp & 1;
    const int m_off = mw * 32, n_off = nw * 64;
    const int p0 = blockIdx.x * 256, co0 = blockIdx.y * 128;
    const int W = 1 << lw, W2 = W + 2, R = 256 >> lw;
    const int ASLAB = (R + 2) * W2 * 32;
    const int STAGE = ASLAB + 36864;

    if (tid < 128) { s_sum[tid] = 0.f; s_sq[tid] = 0.f; }

    const int n_img = p0 >> (2 * lw);
    const int y0    = (p0 >> lw) & (W - 1);
    const char* aBase = (const char*)g_acti[sPrev] + off;
    const int nb0 = co0 >> 3;

    // fill chunks (16B): A slab rows (2 halves each) then B taps
    const int nA = (R + 2) * W2 * 2, ntot = nA + 2304;
    const char* csrc[7]; unsigned cdst[7]; int ckst[7]; int cnt = 0;
#pragma unroll
    for (int k = 0; k < 7; k++) {
        int c = tid + k * 512;
        if (c >= ntot) break;
        if (c < nA) {
            int e = c >> 1, h = c & 1;
            int ry = e / W2, cx = e - ry * W2;
            csrc[cnt] = aBase + (long long)((n_img * W2 + y0 + ry) * W2 + cx) * 256 + h * 16;
            cdst[cnt] = (unsigned)(e * 32 + ((h ^ ((cx >> 2) & 1)) << 4));
            ckst[cnt] = 32;
        } else {
            int b = c - nA, tap = b >> 8, rest = b & 255;
            csrc[cnt] = (const char*)g_wf + (long long)(tap * 8192 + nb0 * 32 + rest * 2) * 8;
            cdst[cnt] = (unsigned)(ASLAB + tap * 4096 + rest * 16);
            ckst[cnt] = 8192;
        }
        cnt++;
    }
    const unsigned smbase = su32(dynsmem);

#define FILL(kc_) {                                                             \
    unsigned sb_ = smbase + ((kc_) % 3) * STAGE;                                \
    for (int i_ = 0; i_ < cnt; i_++)                                            \
        asm volatile("cp.async.cg.shared.global [%0],[%1],16;\n"                \
            :: "r"(sb_ + cdst[i_]), "l"(csrc[i_] + (kc_) * ckst[i_]));          \
    asm volatile("cp.async.commit_group;\n"); }

    // ldmatrix bases: 2 m16 tiles per warp
    int em[2], xm[2];
    const int hh = lane >> 4;
#pragma unroll
    for (int ms = 0; ms < 2; ms++) {
        int pt = m_off + ms * 16 + (lane & 15);
        int ry = pt >> lw, x = pt & (W - 1);
        em[ms] = ry * W2 + x;
        xm[ms] = x;
    }

    int acc[2][8][4];
#pragma unroll
    for (int i = 0; i < 2; i++)
#pragma unroll
        for (int j = 0; j < 8; j++)
#pragma unroll
            for (int k = 0; k < 4; k++) acc[i][j][k] = 0;

    FILL(0); FILL(1);
    for (int kc = 0; kc < 8; kc++) {
        if (kc == 7) asm volatile("cp.async.wait_group 0;\n" ::);
        else         asm volatile("cp.async.wait_group 1;\n" ::);
        __syncthreads();
        if (kc + 2 < 8) FILL(kc + 2);

        const unsigned Ac = smbase + (kc % 3) * STAGE;
        const char*    Bc = dynsmem + (kc % 3) * STAGE + ASLAB;

#pragma unroll
        for (int tap = 0; tap < 9; tap++) {
            const int ky = tap / 3, kx = tap - 3 * (tap / 3);
            uint2 bq[8];
            const uint2* bp = (const uint2*)(Bc + tap * 4096 + nw * 2048 + lane * 8);
#pragma unroll
            for (int j = 0; j < 8; j++) bq[j] = bp[j * 32];

            unsigned am[2][4];
#pragma unroll
            for (int ms = 0; ms < 2; ms++) {
                int cx = xm[ms] + kx;
                unsigned ad = Ac + (unsigned)((em[ms] + ky * W2 + kx) * 32)
                                 + (unsigned)((hh ^ ((cx >> 2) & 1)) << 4);
                asm volatile("ldmatrix.sync.aligned.m8n8.x4.shared.b16 {%0,%1,%2,%3},[%4];\n"
                             : "=r"(am[ms][0]), "=r"(am[ms][1]),
                               "=r"(am[ms][2]), "=r"(am[ms][3]) : "r"(ad));
            }
#pragma unroll
            for (int ns = 0; ns < 8; ns++) {
                IMMA_(acc[0][ns], am[0], bq[ns]);
                IMMA_(acc[1][ns], am[1], bq[ns]);
            }
        }
    }
#undef FILL

    // ---- epilogue ----
    const float a0c = alpha[t * 6];
    int slots[4] = { s1, s2, s3, s4 };
    float coef[4] = { 0.f, 0.f, 0.f, 0.f };
    for (int d = 1; d <= nhist; d++) coef[d - 1] = alpha[t * 6 + 6 - d] * 0.015625f;

    float cs[16], cq[16];
#pragma unroll
    for (int j = 0; j < 16; j++) { cs[j] = 0.f; cq[j] = 0.f; }

#pragma unroll
    for (int ms = 0; ms < 2; ms++) {
#pragma unroll
        for (int half = 0; half < 2; half++) {
            int pe  = p0 + m_off + ms * 16 + g + half * 8;
            int ne  = pe >> (2 * lw);
            int rme = pe & ((1 << (2 * lw)) - 1);
            int ye = rme >> lw, xe = rme & (W - 1);
            long long hb = (long long)off + ((long long)(ne * W2 + ye + 1) * W2 + xe + 1) * 256
                           + co0 + n_off + 2 * qd;
            long long sb2 = (long long)pe * 256 + co0 + n_off + 2 * qd;
#pragma unroll
            for (int ns = 0; ns < 8; ns++) {
                float v0 = a0c * fmaxf((float)acc[ms][ns][half * 2 + 0] * 0.000244140625f, 0.f);
                float v1 = a0c * fmaxf((float)acc[ms][ns][half * 2 + 1] * 0.000244140625f, 0.f);
                for (int d = nhist; d >= 1; d--) {
                    char2 hv = *(const char2*)&g_acti[slots[d - 1]][hb + ns * 8];
                    v0 += coef[d - 1] * (float)hv.x;
                    v1 += coef[d - 1] * (float)hv.y;
                }
                *(float2*)&g_scratch[sb2 + ns * 8] = make_float2(v0, v1);
                cs[ns * 2 + 0] += v0;      cs[ns * 2 + 1] += v1;
                cq[ns * 2 + 0] += v0 * v0; cq[ns * 2 + 1] += v1 * v1;
            }
        }
    }
#pragma unroll
    for (int m = 4; m < 32; m <<= 1) {
#pragma unroll
        for (int j = 0; j < 16; j++) {
            cs[j] += __shfl_xor_sync(0xffffffffu, cs[j], m);
            cq[j] += __shfl_xor_sync(0xffffffffu, cq[j], m);
        }
    }
    if (lane < 4) {
#pragma unroll
        for (int ns = 0; ns < 8; ns++) {
            int ch = n_off + ns * 8 + 2 * lane;
            atomicAdd(&s_sum[ch],     cs[ns * 2 + 0]);
            atomicAdd(&s_sum[ch + 1], cs[ns * 2 + 1]);
            atomicAdd(&s_sq[ch],      cq[ns * 2 + 0]);
            atomicAdd(&s_sq[ch + 1],  cq[ns * 2 + 1]);
        }
    }
    __syncthreads();
    if (tid < 128) {
        atomicAdd(&g_sum[co0 + tid],   (double)s_sum[tid]);
        atomicAdd(&g_sqsum[co0 + tid], (double)s_sq[tid]);
    }
}

// ---------------------------------------------------------------------------
// Small conv (res8): tap-major, CTA 256 thr, M128 x N128, 72 stages.
// ---------------------------------------------------------------------------
__global__ void __launch_bounds__(256, 2) k_conv_small(
    int sPrev, int s1, int s2, int s3, int s4, int nhist,
    unsigned long long off, int lw,
    const float* __restrict__ alpha, int t)
{
    constexpr int S   = 72;
    constexpr int STB = 4096;
    __shared__ __align__(256) char As[3 * STB];
    __shared__ float s_sum[128], s_sq[128];

    const int tid = threadIdx.x, warp = tid >> 5, lane = tid & 31;
    const int g = lane >> 2, qd = lane & 3;
    const int mw = warp >> 1, nw = warp & 1;
    const int m_off = mw * 32, n_off = nw * 64;
    const int p0 = blockIdx.x * 128, co0 = blockIdx.y * 128;
    const int W = 1 << lw, W2 = W + 2;

    if (tid < 128) { s_sum[tid] = 0.f; s_sq[tid] = 0.f; }

    const int r = tid >> 1, h = tid & 1;
    int p  = p0 + r;
    int n  = p >> (2 * lw);
    int rm = p & ((1 << (2 * lw)) - 1);
    int yy = rm >> lw, xx = rm & (W - 1);
    const char* base0 = (const char*)g_acti[sPrev] + off;
    const char* rowp[3];
#pragma unroll
    for (int ky = 0; ky < 3; ky++)
        rowp[ky] = base0 + (long long)((n * W2 + yy + ky) * W2 + xx) * 256 + h * 16;

    const int rr = r & 7;
    const unsigned dstb = su32(As) + (r >> 3) * 256 + ((rr * 2 + (h ^ ((rr >> 2) & 1))) << 4);
    const int rl = m_off + (lane & 15), hh = lane >> 4, rlr = rl & 7;
    const unsigned ldsb = su32(As) + (rl >> 3) * 256 + ((rlr * 2 + (hh ^ ((rlr >> 2) & 1))) << 4);
    const int nb0 = (co0 >> 3) + nw * 8;

#define CPA(s_, ph_) {                                                          \
    int tap_ = (s_) >> 3, kc_ = (s_) & 7;                                       \
    int ky_ = (tap_ * 11) >> 5; int kx_ = tap_ - 3 * ky_;                       \
    const char* src_ = rowp[ky_] + kx_ * 256 + kc_ * 32;                        \
    asm volatile("cp.async.cg.shared.global [%0],[%1],16;\n"                    \
                 :: "r"(dstb + (ph_) * STB), "l"(src_));                        \
    asm volatile("cp.async.commit_group;\n"); }

#define LDB(dst) {                                                              \
    dst[0] = wptr[0];   dst[1] = wptr[32];  dst[2] = wptr[64];  dst[3] = wptr[96]; \
    dst[4] = wptr[128]; dst[5] = wptr[160]; dst[6] = wptr[192]; dst[7] = wptr[224]; \
    wptr += 1024; }

    int acc[2][8][4];
#pragma unroll
    for (int i = 0; i < 2; i++)
#pragma unroll
        for (int j = 0; j < 8; j++)
#pragma unroll
            for (int k = 0; k < 4; k++) acc[i][j][k] = 0;

    uint2 bA[8], bB[8];
    const uint2* wptr = g_wf + nb0 * 32 + lane;
    LDB(bA);
    CPA(0, 0); CPA(1, 1);

#define BODY(j_, CUR, NXT) {                                                    \
    int s_ = sb + (j_);                                                         \
    if (s_ == S - 1) asm volatile("cp.async.wait_group 0;\n" ::);               \
    else             asm volatile("cp.async.wait_group 1;\n" ::);               \
    __syncthreads();                                                            \
    if (s_ + 2 < S) CPA(s_ + 2, ((j_) + 2) % 3);                                \
    if (s_ + 1 < S) LDB(NXT);                                                   \
    unsigned a0[4], a1[4];                                                      \
    unsigned base_ = ldsb + ((j_) % 3) * STB;                                   \
    asm volatile("ldmatrix.sync.aligned.m8n8.x4.shared.b16 {%0,%1,%2,%3},[%4];\n" \
                 : "=r"(a0[0]), "=r"(a0[1]), "=r"(a0[2]), "=r"(a0[3]) : "r"(base_)); \
    asm volatile("ldmatrix.sync.aligned.m8n8.x4.shared.b16 {%0,%1,%2,%3},[%4];\n" \
                 : "=r"(a1[0]), "=r"(a1[1]), "=r"(a1[2]), "=r"(a1[3]) : "r"(base_ + 512)); \
    _Pragma("unroll")                                                           \
    for (int ns = 0; ns < 8; ns++) {                                            \
        IMMA_(acc[0][ns], a0, CUR[ns]);                                         \
        IMMA_(acc[1][ns], a1, CUR[ns]);                                         \
    } }

    for (int sb = 0; sb < S; sb += 6) {
        BODY(0, bA, bB); BODY(1, bB, bA); BODY(2, bA, bB);
        BODY(3, bB, bA); BODY(4, bA, bB); BODY(5, bB, bA);
    }
#undef BODY
#undef CPA
#undef LDB

    const float a0c = alpha[t * 6];
    int slots[4] = { s1, s2, s3, s4 };
    float coef[4] = { 0.f, 0.f, 0.f, 0.f };
    for (int d = 1; d <= nhist; d++) coef[d - 1] = alpha[t * 6 + 6 - d] * 0.015625f;

    float cs[16], cq[16];
#pragma unroll
    for (int j = 0; j < 16; j++) { cs[j] = 0.f; cq[j] = 0.f; }

#pragma unroll
    for (int ms = 0; ms < 2; ms++) {
#pragma unroll
        for (int half = 0; half < 2; half++) {
            int pe  = p0 + m_off + ms * 16 + g + half * 8;
            int ne  = pe >> (2 * lw);
            int rme = pe & ((1 << (2 * lw)) - 1);
            int ye = rme >> lw, xe = rme & (W - 1);
            long long hb = (long long)off + ((long long)(ne * W2 + ye + 1) * W2 + xe + 1) * 256
                           + co0 + n_off + 2 * qd;
            long long sb2 = (long long)pe * 256 + co0 + n_off + 2 * qd;
#pragma unroll
            for (int ns = 0; ns < 8; ns++) {
                float v0 = a0c * fmaxf((float)acc[ms][ns][half * 2 + 0] * 0.000244140625f, 0.f);
                float v1 = a0c * fmaxf((float)acc[ms][ns][half * 2 + 1] * 0.000244140625f, 0.f);
                for (int d = nhist; d >= 1; d--) {
                    char2 hv = *(const char2*)&g_acti[slots[d - 1]][hb + ns * 8];
                    v0 += coef[d - 1] * (float)hv.x;
                    v1 += coef[d - 1] * (float)hv.y;
                }
                *(float2*)&g_scratch[sb2 + ns * 8] = make_float2(v0, v1);
                cs[ns * 2 + 0] += v0;      cs[ns * 2 + 1] += v1;
                cq[ns * 2 + 0] += v0 * v0; cq[ns * 2 + 1] += v1 * v1;
            }
        }
    }
#pragma unroll
    for (int m = 4; m < 32; m <<= 1) {
#pragma unroll
        for (int j = 0; j < 16; j++) {
            cs[j] += __shfl_xor_sync(0xffffffffu, cs[j], m);
            cq[j] += __shfl_xor_sync(0xffffffffu, cq[j], m);
        }
    }
    if (lane < 4) {
#pragma unroll
        for (int ns = 0; ns < 8; ns++) {
            int ch = n_off + ns * 8 + 2 * lane;
            atomicAdd(&s_sum[ch],     cs[ns * 2 + 0]);
            atomicAdd(&s_sum[ch + 1], cs[ns * 2 + 1]);
            atomicAdd(&s_sq[ch],      cq[ns * 2 + 0]);
            atomicAdd(&s_sq[ch + 1],  cq[ns * 2 + 1]);
        }
    }
    __syncthreads();
    if (tid < 128) {
        atomicAdd(&g_sum[co0 + tid],   (double)s_sum[tid]);
        atomicAdd(&g_sqsum[co0 + tid], (double)s_sq[tid]);
    }
}

__global__ void k_stats(double invP) {
    int c = threadIdx.x;
    double mu  = g_sum[c] * invP;
    double var = g_sqsum[c] * invP - mu * mu;
    g_mu[c]   = (float)mu;
    g_rstd[c] = rsqrtf((float)var + 1e-5f);
    g_sum[c] = 0.0; g_sqsum[c] = 0.0;
}

// BN + trunc-quantize -> int8 q (value q/64), zero halo
__global__ void k_bnq(int sd, unsigned long long doff, int H, int W,
                      const float* __restrict__ gamma, const float* __restrict__ beta)
{
    int W2 = W + 2, H2 = H + 2;
    long long total = (long long)32 * H2 * W2 * 128;
    long long e = (long long)blockIdx.x * 256 + threadIdx.x;
    if (e >= total) return;
    int cp = (int)(e & 127); int c = cp * 2;
    long long r = e >> 7;
    int px = (int)(r % W2); r /= W2;
    int py = (int)(r % H2); int n = (int)(r / H2);
    char2 outv; outv.x = 0; outv.y = 0;
    if (py >= 1 && py <= H && px >= 1 && px <= W) {
        const float2 v = *(const float2*)&g_scratch[((((long long)n * H + (py - 1)) * W + (px - 1)) << 8) + c];
        float b0 = gamma[c]     * ((v.x - g_mu[c])     * g_rstd[c])     + beta[c];
        float b1 = gamma[c + 1] * ((v.y - g_mu[c + 1]) * g_rstd[c + 1]) + beta[c + 1];
        outv.x = (signed char)(int)truncf(b0 * 0.015625f);
        outv.y = (signed char)(int)truncf(b1 * 0.015625f);
    }
    *(char2*)(&g_acti[sd][doff + (e << 1)]) = outv;
}

__global__ void k_pool4(int spack, unsigned long long soff, unsigned long long doff,
                        int H, int W)
{
    int s = (spack >> (blockIdx.y * 8)) & 0xff;
    int W2 = W + 2, H2 = H + 2, SW2 = 2 * W + 2;
    long long total = (long long)32 * H2 * W2 * 128;
    long long e = (long long)blockIdx.x * 256 + threadIdx.x;
    if (e >= total) return;
    int cp = (int)(e & 127);
    long long r = e >> 7;
    int px = (int)(r % W2); r /= W2;
    int py = (int)(r % H2); int n = (int)(r / H2);
    char2 o; o.x = 0; o.y = 0;
    if (py >= 1 && py <= H && px >= 1 && px <= W) {
        const signed char* base = g_acti[s] + soff;
        long long i00 = (((long long)n * (2 * H + 2) + (2 * py - 1)) * SW2 + (2 * px - 1)) * 256 + cp * 2;
        long long rs = (long long)SW2 * 256;
        char2 v00 = *(const char2*)(base + i00);
        char2 v01 = *(const char2*)(base + i00 + 256);
        char2 v10 = *(const char2*)(base + i00 + rs);
        char2 v11 = *(const char2*)(base + i00 + rs + 256);
        o.x = (signed char)max(max((int)v00.x, (int)v01.x), max((int)v10.x, (int)v11.x));
        o.y = (signed char)max(max((int)v00.y, (int)v01.y), max((int)v10.y, (int)v11.y));
    }
    *(char2*)(g_acti[s] + doff + (e << 1)) = o;
}

__global__ void k_feat(int s, unsigned long long off) {
    int id = blockIdx.x * 256 + threadIdx.x;
    int n = id >> 8, c = id & 255;
    const signed char* base = g_acti[s] + off;
    int m = -1000;
    for (int yy = 0; yy < 8; yy++)
        for (int xx = 0; xx < 8; xx++) {
            int v = base[(((long long)n * 10 + (yy + 1)) * 10 + (xx + 1)) * 256 + c];
            m = max(m, v);
        }
    g_feat[id] = (float)m * 0.015625f;
}

__global__ void k_lin(const float* __restrict__ lw, const float* __restrict__ lb,
                      float* __restrict__ out) {
    __shared__ float fs[256];
    int n = blockIdx.y;
    int cls = blockIdx.x * 256 + threadIdx.x;
    fs[threadIdx.x] = g_feat[n * 256 + threadIdx.x];
    __syncthreads();
    if (cls < 1000) {
        float a = 0.f;
#pragma unroll 8
        for (int c = 0; c < 256; c++) a += fs[c] * lw[cls * 256 + c];
        out[n * 1000 + cls] = a + lb[cls];
    }
}

// ---------------------------------------------------------------------------
extern "C" void kernel_launch(void* const* d_in, const int* in_sizes, int n_in,
                              void* d_out, int out_size)
{
    const float* x      = (const float*)d_in[0];
    const float* conv_w = (const float*)d_in[1];
    const float* lin_w  = (const float*)d_in[2];
    const float* lin_b  = (const float*)d_in[3];
    const float* alpha  = (const float*)d_in[4];
    const float* gmm    = (const float*)d_in[5];
    const float* bta    = (const float*)d_in[6];
    float* out = (float*)d_out;

    cudaFuncSetAttribute(k_conv, cudaFuncAttributeMaxDynamicSharedMemorySize, 148608);

    k_prep_w<<<288, 256>>>(conv_w);
    k_prep_in<<<139392, 256>>>(x);

    static const int S1[10]  = {0,1,2,3,4,5,0,1,2,3};
    static const int S2[10]  = {0,0,1,2,3,4,5,0,1,2};
    static const int S3[10]  = {0,0,0,1,2,3,4,5,0,1};
    static const int S4[10]  = {0,0,0,0,1,2,3,4,5,0};
    static const int NH[10]  = {1,2,3,4,4,4,4,4,4,4};
    static const int DST[10] = {1,2,3,4,5,0,1,2,3,4};
    static const int HH[10]  = {64,64,64,32,32,32,16,16,16,8};
    static const int LW[10]  = {6,6,6,5,5,5,4,4,4,3};
    static const unsigned long long OFFT[10] =
        {OFF64,OFF64,OFF64,OFF32,OFF32,OFF32,OFF16,OFF16,OFF16,OFF8};

    for (int t = 0; t < 10; t++) {
        int H = HH[t], W = H, P = 32 * H * W;
        unsigned long long off = OFFT[t];
        if (t < 9) {
            int R = 256 / W, W2 = W + 2;
            int dsm = 3 * ((R + 2) * W2 * 32 + 36864);
            dim3 cg(P / 256, 2);
            k_conv<<<cg, 512, dsm>>>(S1[t], S1[t], S2[t], S3[t], S4[t], NH[t],
                                     off, LW[t], alpha, t);
        } else {
            dim3 cg(P / 128, 2);
            k_conv_small<<<cg, 256>>>(S1[t], S1[t], S2[t], S3[t], S4[t], NH[t],
                                      off, LW[t], alpha, t);
        }
        k_stats<<<1, 256>>>(1.0 / (double)P);
        long long tot = (long long)32 * (H + 2) * (W + 2) * 128;
        k_bnq<<<(unsigned)((tot + 255) / 256), 256>>>(DST[t], off, H, W,
                                                      gmm + t * 256, bta + t * 256);
        if (t == 2 || t == 5 || t == 8) {
            int Hd = H / 2, Wd = Hd;
            unsigned long long doff = (t == 2) ? OFF32 : (t == 5) ? OFF16 : OFF8;
            long long pt = (long long)32 * (Hd + 2) * (Wd + 2) * 128;
            int spack = (t == 5) ? (3 | (4 << 8) | (5 << 16) | (0 << 24))
                                 : (0 | (1 << 8) | (2 << 16) | (3 << 24));
            dim3 pg((unsigned)((pt + 255) / 256), 4);
            k_pool4<<<pg, 256>>>(spack, off, doff, Hd, Wd);
        }
    }
    k_feat<<<32, 256>>>(4, OFF8);
    k_lin<<<dim3(4, 32), 256>>>(lin_w, lin_b, out);
}

// round 13
// speedup vs baseline: 1.9487x; 1.9487x over previous
#include <cuda_runtime.h>
#include <cuda_bf16.h>
#include <cstdint>

#define SLOT_ELEMS 45154304ull
#define OFF64 0ull
#define OFF32 35684352ull
#define OFF16 0ull
#define OFF8  4000000ull

__device__ __align__(16) __nv_bfloat16 g_act[6][SLOT_ELEMS];
__device__ __align__(16) float         g_scratch[33554432];   // fp32 pre-BN [pixel][256]
__device__ __align__(16) uint2         g_wf[147456];          // [tap][kc][P][lane][which]
__device__ double g_sumA[2560];
__device__ double g_sqA[2560];

__device__ __forceinline__ unsigned su32(const void* p) {
    return (unsigned)__cvta_generic_to_shared(p);
}

#define MMA_(c, a, b)                                                           \
    asm volatile("mma.sync.aligned.m16n8k16.row.col.f32.bf16.bf16.f32 "         \
                 "{%0,%1,%2,%3},{%4,%5,%6,%7},{%8,%9},{%0,%1,%2,%3};\n"         \
                 : "+f"(c[0]), "+f"(c[1]), "+f"(c[2]), "+f"(c[3])               \
                 : "r"(a[0]), "r"(a[1]), "r"(a[2]), "r"(a[3]),                  \
                   "r"(b.x), "r"(b.y))

// conv_w (OIHW fp32, int/64) -> paired-fragment layout:
// uint2 index = ((tap*16+kc)*16+P)*64 + lane*2 + which ; frag for cout-block nb=2P+which
__global__ void k_prep_w(const float* __restrict__ cw) {
    int idx = blockIdx.x * 256 + threadIdx.x;
    if (idx < 2560) { g_sumA[idx] = 0.0; g_sqA[idx] = 0.0; }
    if (idx >= 147456) return;
    int tap = idx >> 14;
    int rem = idx & 16383;
    int kc  = rem >> 10;
    int r2  = rem & 1023;
    int P   = r2 >> 6;
    int l2  = r2 & 63;
    int lane = l2 >> 1, which = l2 & 1;
    int nb = 2 * P + which;
    int g = lane >> 2, qd = lane & 3;
    int co = nb * 8 + g, ci0 = kc * 16 + 2 * qd;
    __nv_bfloat162 lo, hi;
    lo.x = __float2bfloat16(cw[(co * 256 + ci0    ) * 9 + tap]);
    lo.y = __float2bfloat16(cw[(co * 256 + ci0 + 1) * 9 + tap]);
    hi.x = __float2bfloat16(cw[(co * 256 + ci0 + 8) * 9 + tap]);
    hi.y = __float2bfloat16(cw[(co * 256 + ci0 + 9) * 9 + tap]);
    uint2 v;
    v.x = *(unsigned*)&lo;
    v.y = *(unsigned*)&hi;
    g_wf[idx] = v;
}

// x (32,3,64,64) fp32 -> quantize (v=64), pad ch->256, padded NHWC bf16 slot0
__global__ void k_prep_in(const float* __restrict__ x) {
    long long e = (long long)blockIdx.x * 256 + threadIdx.x;
    if (e >= 35684352ll) return;
    int c = (int)(e & 255);
    long long r = e >> 8;
    int px = (int)(r % 66); r /= 66;
    int py = (int)(r % 66); int n = (int)(r / 66);
    float v = 0.f;
    if (py >= 1 && py <= 64 && px >= 1 && px <= 64 && c < 3) {
        float xv = x[(((long long)n * 3 + c) * 64 + (py - 1)) * 64 + (px - 1)];
        v = truncf(xv * 0.015625f) * 0.015625f;
    }
    g_act[0][e] = __float2bfloat16(v);
}

// ---------------------------------------------------------------------------
// Big conv (t<9): CTA 512 thr, 16 warps (8M x 2N), warp M32 x N64.
// Tile M256 x N128, K=2304, 16 kc-stages, triple-buffered cp.async.
// B read as 4 x LDS.128 per tap per warp (conflict-free paired layout).
// ---------------------------------------------------------------------------
__global__ void __launch_bounds__(512, 1) k_conv(
    int sPrev, int s1, int s2, int s3, int s4, int nhist,
    unsigned long long off, int lw,
    const float* __restrict__ alpha, int t)
{
    extern __shared__ __align__(16) char dynsmem[];
    __shared__ float s_sum[128], s_sq[128];

    const int tid = threadIdx.x, warp = tid >> 5, lane = tid & 31;
    const int g = lane >> 2, qd = lane & 3;
    const int mw = warp >> 1, nw = warp & 1;
    const int m_off = mw * 32, n_off = nw * 64;
    const int p0 = blockIdx.x * 256, co0 = blockIdx.y * 128;
    const int W = 1 << lw, W2 = W + 2, R = 256 >> lw;
    const int ASLAB = (R + 2) * W2 * 32;
    const int STAGE = ASLAB + 36864;

    if (tid < 128) { s_sum[tid] = 0.f; s_sq[tid] = 0.f; }

    const int n_img = p0 >> (2 * lw);
    const int y0    = (p0 >> lw) & (W - 1);
    const char* aBase = (const char*)(g_act[sPrev] + off);

    // fill chunks (16B each): A slab rows then B taps
    const int nA = (R + 2) * W2 * 2, ntot = nA + 2304;
    const char* csrc[7]; unsigned cdst[7]; int ckst[7]; int cnt = 0;
#pragma unroll
    for (int k = 0; k < 7; k++) {
        int c = tid + k * 512;
        if (c >= ntot) break;
        if (c < nA) {
            int e = c >> 1, h = c & 1;
            int ry = e / W2, cx = e - ry * W2;
            csrc[cnt] = aBase + (long long)((n_img * W2 + y0 + ry) * W2 + cx) * 512 + h * 16;
            cdst[cnt] = (unsigned)(e * 32 + ((h ^ ((cx >> 2) & 1)) << 4));
            ckst[cnt] = 32;
        } else {
            int b = c - nA, tap = b >> 8, rest = b & 255;   // rest = pp*32+lane
            csrc[cnt] = (const char*)g_wf + tap * 131072 + (co0 >> 4) * 512 + rest * 16;
            cdst[cnt] = (unsigned)(ASLAB + tap * 4096 + rest * 16);
            ckst[cnt] = 8192;
        }
        cnt++;
    }
    const unsigned smbase = su32(dynsmem);

#define ISSUE(kc_) {                                                            \
    unsigned sb_ = smbase + ((kc_) % 3) * STAGE;                                \
    for (int i_ = 0; i_ < cnt; i_++)                                            \
        asm volatile("cp.async.cg.shared.global [%0],[%1],16;\n"                \
            :: "r"(sb_ + cdst[i_]), "l"(csrc[i_] + (kc_) * ckst[i_]));          \
    asm volatile("cp.async.commit_group;\n"); }

    // ldmatrix bases: 2 m16 tiles per warp
    int em[2], xm[2];
    const int hh = lane >> 4;
#pragma unroll
    for (int ms = 0; ms < 2; ms++) {
        int pt = m_off + ms * 16 + (lane & 15);
        int ry = pt >> lw, x = pt & (W - 1);
        em[ms] = ry * W2 + x;
        xm[ms] = x;
    }

    float acc[2][8][4];
#pragma unroll
    for (int i = 0; i < 2; i++)
#pragma unroll
        for (int j = 0; j < 8; j++)
#pragma unroll
            for (int k = 0; k < 4; k++) acc[i][j][k] = 0.f;

    ISSUE(0);
    for (int kc = 0; kc < 16; kc++) {
        if (kc < 15) { ISSUE(kc + 1); asm volatile("cp.async.wait_group 1;\n" ::); }
        else         { asm volatile("cp.async.wait_group 0;\n" ::); }
        __syncthreads();

        const unsigned Ac = smbase + (kc % 3) * STAGE;
        const char*    Bc = dynsmem + (kc % 3) * STAGE + ASLAB;

#pragma unroll
        for (int tap = 0; tap < 9; tap++) {
            const int ky = tap / 3, kx = tap - 3 * (tap / 3);
            uint2 bq[8];
            const uint4* bp = (const uint4*)(Bc + tap * 4096 + nw * 2048 + lane * 16);
#pragma unroll
            for (int j = 0; j < 4; j++) {
                uint4 q = bp[j * 32];
                bq[2 * j]     = make_uint2(q.x, q.y);
                bq[2 * j + 1] = make_uint2(q.z, q.w);
            }
            unsigned am[2][4];
#pragma unroll
            for (int ms = 0; ms < 2; ms++) {
                int cx = xm[ms] + kx;
                unsigned ad = Ac + (unsigned)((em[ms] + ky * W2 + kx) * 32)
                                 + (unsigned)((hh ^ ((cx >> 2) & 1)) << 4);
                asm volatile("ldmatrix.sync.aligned.m8n8.x4.shared.b16 {%0,%1,%2,%3},[%4];\n"
                             : "=r"(am[ms][0]), "=r"(am[ms][1]),
                               "=r"(am[ms][2]), "=r"(am[ms][3]) : "r"(ad));
            }
#pragma unroll
            for (int ns = 0; ns < 8; ns++) {
                MMA_(acc[0][ns], am[0], bq[ns]);
                MMA_(acc[1][ns], am[1], bq[ns]);
            }
        }
    }
#undef ISSUE

    // ---- epilogue ----
    const float a0c = alpha[t * 6];
    int slots[4] = { s1, s2, s3, s4 };
    float coef[4] = { 0.f, 0.f, 0.f, 0.f };
    for (int d = 1; d <= nhist; d++) coef[d - 1] = alpha[t * 6 + 6 - d];

    float cs[16], cq[16];
#pragma unroll
    for (int j = 0; j < 16; j++) { cs[j] = 0.f; cq[j] = 0.f; }

#pragma unroll
    for (int ms = 0; ms < 2; ms++) {
#pragma unroll
        for (int half = 0; half < 2; half++) {
            int pe  = p0 + m_off + ms * 16 + g + half * 8;
            int ne  = pe >> (2 * lw);
            int rme = pe & ((1 << (2 * lw)) - 1);
            int ye = rme >> lw, xe = rme & (W - 1);
            long long hb = (long long)off + ((long long)(ne * W2 + ye + 1) * W2 + xe + 1) * 256
                           + co0 + n_off + 2 * qd;
            long long sb2 = (long long)pe * 256 + co0 + n_off + 2 * qd;
#pragma unroll
            for (int ns = 0; ns < 8; ns++) {
                float v0 = a0c * fmaxf(acc[ms][ns][half * 2 + 0], 0.f);
                float v1 = a0c * fmaxf(acc[ms][ns][half * 2 + 1], 0.f);
                for (int d = nhist; d >= 1; d--) {
                    __nv_bfloat162 hv = *(const __nv_bfloat162*)&g_act[slots[d - 1]][hb + ns * 8];
                    v0 += coef[d - 1] * __bfloat162float(hv.x);
                    v1 += coef[d - 1] * __bfloat162float(hv.y);
                }
                *(float2*)&g_scratch[sb2 + ns * 8] = make_float2(v0, v1);
                cs[ns * 2 + 0] += v0;      cs[ns * 2 + 1] += v1;
                cq[ns * 2 + 0] += v0 * v0; cq[ns * 2 + 1] += v1 * v1;
            }
        }
    }
#pragma unroll
    for (int m = 4; m < 32; m <<= 1) {
#pragma unroll
        for (int j = 0; j < 16; j++) {
            cs[j] += __shfl_xor_sync(0xffffffffu, cs[j], m);
            cq[j] += __shfl_xor_sync(0xffffffffu, cq[j], m);
        }
    }
    if (lane < 4) {
#pragma unroll
        for (int ns = 0; ns < 8; ns++) {
            int ch = n_off + ns * 8 + 2 * lane;
            atomicAdd(&s_sum[ch],     cs[ns * 2 + 0]);
            atomicAdd(&s_sum[ch + 1], cs[ns * 2 + 1]);
            atomicAdd(&s_sq[ch],      cq[ns * 2 + 0]);
            atomicAdd(&s_sq[ch + 1],  cq[ns * 2 + 1]);
        }
    }
    __syncthreads();
    if (tid < 128) {
        atomicAdd(&g_sumA[t * 256 + co0 + tid], (double)s_sum[tid]);
        atomicAdd(&g_sqA [t * 256 + co0 + tid], (double)s_sq[tid]);
    }
}

// ---------------------------------------------------------------------------
// Small conv (res8): tap-major, CTA 256 thr, M128 x N128, 144 stages.
// ---------------------------------------------------------------------------
__global__ void __launch_bounds__(256, 2) k_conv_small(
    int sPrev, int s1, int s2, int s3, int s4, int nhist,
    unsigned long long off, int lw,
    const float* __restrict__ alpha, int t)
{
    constexpr int S   = 144;
    constexpr int STB = 4096;
    __shared__ __align__(256) char As[3 * STB];
    __shared__ float s_sum[128], s_sq[128];

    const int tid = threadIdx.x, warp = tid >> 5, lane = tid & 31;
    const int g = lane >> 2, qd = lane & 3;
    const int mw = warp >> 1, nw = warp & 1;
    const int m_off = mw * 32, n_off = nw * 64;
    const int p0 = blockIdx.x * 128, co0 = blockIdx.y * 128;
    const int W = 1 << lw, W2 = W + 2;

    if (tid < 128) { s_sum[tid] = 0.f; s_sq[tid] = 0.f; }

    const int r = tid >> 1, h = tid & 1;
    int p  = p0 + r;
    int n  = p >> (2 * lw);
    int rm = p & ((1 << (2 * lw)) - 1);
    int yy = rm >> lw, xx = rm & (W - 1);
    const __nv_bfloat16* hp = g_act[sPrev] + off;
    const char* rowp[3];
#pragma unroll
    for (int ky = 0; ky < 3; ky++)
        rowp[ky] = (const char*)(hp + ((long long)(n * W2 + yy + ky) * W2 + xx) * 256 + h * 8);

    const int rr = r & 7;
    const unsigned dstb = su32(As) + (r >> 3) * 256 + ((rr * 2 + (h ^ ((rr >> 2) & 1))) << 4);
    const int rl = m_off + (lane & 15), hh = lane >> 4, rlr = rl & 7;
    const unsigned ldsb = su32(As) + (rl >> 3) * 256 + ((rlr * 2 + (hh ^ ((rlr >> 2) & 1))) << 4);

#define CPA(s_, ph_) {                                                          \
    int tap_ = (s_) >> 4, kc_ = (s_) & 15;                                      \
    int ky_ = (tap_ * 11) >> 5; int kx_ = tap_ - 3 * ky_;                       \
    const char* src_ = rowp[ky_] + kx_ * 512 + kc_ * 32;                        \
    asm volatile("cp.async.cg.shared.global [%0],[%1],16;\n"                    \
                 :: "r"(dstb + (ph_) * STB), "l"(src_));                        \
    asm volatile("cp.async.commit_group;\n"); }

#define LDB(dst) {                                                              \
    uint4 q0 = wptr[0], q1 = wptr[32], q2 = wptr[64], q3 = wptr[96];            \
    dst[0] = make_uint2(q0.x, q0.y); dst[1] = make_uint2(q0.z, q0.w);           \
    dst[2] = make_uint2(q1.x, q1.y); dst[3] = make_uint2(q1.z, q1.w);           \
    dst[4] = make_uint2(q2.x, q2.y); dst[5] = make_uint2(q2.z, q2.w);           \
    dst[6] = make_uint2(q3.x, q3.y); dst[7] = make_uint2(q3.z, q3.w);           \
    wptr += 512; }

    float acc[2][8][4];
#pragma unroll
    for (int i = 0; i < 2; i++)
#pragma unroll
        for (int j = 0; j < 8; j++)
#pragma unroll
            for (int k = 0; k < 4; k++) acc[i][j][k] = 0.f;

    uint2 bA[8], bB[8];
    const uint4* wptr = (const uint4*)((const char*)g_wf + (co0 >> 4) * 512 + nw * 2048 + lane * 16);
    LDB(bA);
    CPA(0, 0); CPA(1, 1);

#define BODY(j_, CUR, NXT) {                                                    \
    int s_ = sb + (j_);                                                         \
    if (s_ == S - 1) asm volatile("cp.async.wait_group 0;\n" ::);               \
    else             asm volatile("cp.async.wait_group 1;\n" ::);               \
    __syncthreads();                                                            \
    if (s_ + 2 < S) CPA(s_ + 2, ((j_) + 2) % 3);                                \
    if (s_ + 1 < S) LDB(NXT);                                                   \
    unsigned a0[4], a1[4];                                                      \
    unsigned base_ = ldsb + ((j_) % 3) * STB;                                   \
    asm volatile("ldmatrix.sync.aligned.m8n8.x4.shared.b16 {%0,%1,%2,%3},[%4];\n" \
                 : "=r"(a0[0]), "=r"(a0[1]), "=r"(a0[2]), "=r"(a0[3]) : "r"(base_)); \
    asm volatile("ldmatrix.sync.aligned.m8n8.x4.shared.b16 {%0,%1,%2,%3},[%4];\n" \
                 : "=r"(a1[0]), "=r"(a1[1]), "=r"(a1[2]), "=r"(a1[3]) : "r"(base_ + 512)); \
    _Pragma("unroll")                                                           \
    for (int ns = 0; ns < 8; ns++) {                                            \
        MMA_(acc[0][ns], a0, CUR[ns]);                                          \
        MMA_(acc[1][ns], a1, CUR[ns]);                                          \
    } }

    for (int sb = 0; sb < S; sb += 6) {
        BODY(0, bA, bB); BODY(1, bB, bA); BODY(2, bA, bB);
        BODY(3, bB, bA); BODY(4, bA, bB); BODY(5, bB, bA);
    }
#undef BODY
#undef CPA
#undef LDB

    const float a0c = alpha[t * 6];
    int slots[4] = { s1, s2, s3, s4 };
    float coef[4] = { 0.f, 0.f, 0.f, 0.f };
    for (int d = 1; d <= nhist; d++) coef[d - 1] = alpha[t * 6 + 6 - d];

    float cs[16], cq[16];
#pragma unroll
    for (int j = 0; j < 16; j++) { cs[j] = 0.f; cq[j] = 0.f; }

#pragma unroll
    for (int ms = 0; ms < 2; ms++) {
#pragma unroll
        for (int half = 0; half < 2; half++) {
            int pe  = p0 + m_off + ms * 16 + g + half * 8;
            int ne  = pe >> (2 * lw);
            int rme = pe & ((1 << (2 * lw)) - 1);
            int ye = rme >> lw, xe = rme & (W - 1);
            long long hb = (long long)off + ((long long)(ne * W2 + ye + 1) * W2 + xe + 1) * 256
                           + co0 + n_off + 2 * qd;
            long long sb2 = (long long)pe * 256 + co0 + n_off + 2 * qd;
#pragma unroll
            for (int ns = 0; ns < 8; ns++) {
                float v0 = a0c * fmaxf(acc[ms][ns][half * 2 + 0], 0.f);
                float v1 = a0c * fmaxf(acc[ms][ns][half * 2 + 1], 0.f);
                for (int d = nhist; d >= 1; d--) {
                    __nv_bfloat162 hv = *(const __nv_bfloat162*)&g_act[slots[d - 1]][hb + ns * 8];
                    v0 += coef[d - 1] * __bfloat162float(hv.x);
                    v1 += coef[d - 1] * __bfloat162float(hv.y);
                }
                *(float2*)&g_scratch[sb2 + ns * 8] = make_float2(v0, v1);
                cs[ns * 2 + 0] += v0;      cs[ns * 2 + 1] += v1;
                cq[ns * 2 + 0] += v0 * v0; cq[ns * 2 + 1] += v1 * v1;
            }
        }
    }
#pragma unroll
    for (int m = 4; m < 32; m <<= 1) {
#pragma unroll
        for (int j = 0; j < 16; j++) {
            cs[j] += __shfl_xor_sync(0xffffffffu, cs[j], m);
            cq[j] += __shfl_xor_sync(0xffffffffu, cq[j], m);
        }
    }
    if (lane < 4) {
#pragma unroll
        for (int ns = 0; ns < 8; ns++) {
            int ch = n_off + ns * 8 + 2 * lane;
            atomicAdd(&s_sum[ch],     cs[ns * 2 + 0]);
            atomicAdd(&s_sum[ch + 1], cs[ns * 2 + 1]);
            atomicAdd(&s_sq[ch],      cq[ns * 2 + 0]);
            atomicAdd(&s_sq[ch + 1],  cq[ns * 2 + 1]);
        }
    }
    __syncthreads();
    if (tid < 128) {
        atomicAdd(&g_sumA[t * 256 + co0 + tid], (double)s_sum[tid]);
        atomicAdd(&g_sqA [t * 256 + co0 + tid], (double)s_sq[tid]);
    }
}

// BN (stats inline from g_sumA/g_sqA) + trunc-quantize -> padded bf16 (zero halo)
__global__ void k_bnq(int sd, unsigned long long doff, int H, int W,
                      const float* __restrict__ gamma, const float* __restrict__ beta,
                      int t, double invP)
{
    __shared__ float smu[256], srstd[256];
    int tid = threadIdx.x;
    if (tid < 128) {
#pragma unroll
        for (int j = 0; j < 2; j++) {
            int c = 2 * tid + j;
            double mu  = g_sumA[t * 256 + c] * invP;
            double var = g_sqA[t * 256 + c] * invP - mu * mu;
            smu[c]   = (float)mu;
            srstd[c] = rsqrtf((float)var + 1e-5f);
        }
    }
    __syncthreads();
    int W2 = W + 2, H2 = H + 2;
    long long total = (long long)32 * H2 * W2 * 128;
    long long e = (long long)blockIdx.x * 256 + tid;
    if (e >= total) return;
    int cp = (int)(e & 127); int c = cp * 2;
    long long r = e >> 7;
    int px = (int)(r % W2); r /= W2;
    int py = (int)(r % H2); int n = (int)(r / H2);
    __nv_bfloat162 outv;
    if (py >= 1 && py <= H && px >= 1 && px <= W) {
        const float2 v = *(const float2*)&g_scratch[((((long long)n * H + (py - 1)) * W + (px - 1)) << 8) + c];
        float b0 = gamma[c]     * ((v.x - smu[c])     * srstd[c])     + beta[c];
        float b1 = gamma[c + 1] * ((v.y - smu[c + 1]) * srstd[c + 1]) + beta[c + 1];
        outv.x = __float2bfloat16(truncf(b0 * 0.015625f) * 0.015625f);
        outv.y = __float2bfloat16(truncf(b1 * 0.015625f) * 0.015625f);
    } else {
        outv.x = __float2bfloat16(0.f);
        outv.y = __float2bfloat16(0.f);
    }
    *(__nv_bfloat162*)(&g_act[sd][doff + (e << 1)]) = outv;
}

__global__ void k_pool4(int spack, unsigned long long soff, unsigned long long doff,
                        int H, int W)
{
    int s = (spack >> (blockIdx.y * 8)) & 0xff;
    int W2 = W + 2, H2 = H + 2, SW2 = 2 * W + 2;
    long long total = (long long)32 * H2 * W2 * 128;
    long long e = (long long)blockIdx.x * 256 + threadIdx.x;
    if (e >= total) return;
    int cp = (int)(e & 127);
    long long r = e >> 7;
    int px = (int)(r % W2); r /= W2;
    int py = (int)(r % H2); int n = (int)(r / H2);
    __nv_bfloat162 o;
    if (py >= 1 && py <= H && px >= 1 && px <= W) {
        const __nv_bfloat16* base = g_act[s] + soff;
        long long i00 = (((long long)n * (2 * H + 2) + (2 * py - 1)) * SW2 + (2 * px - 1)) * 256 + cp * 2;
        long long rs = (long long)SW2 * 256;
        __nv_bfloat162 v00 = *(const __nv_bfloat162*)(base + i00);
        __nv_bfloat162 v01 = *(const __nv_bfloat162*)(base + i00 + 256);
        __nv_bfloat162 v10 = *(const __nv_bfloat162*)(base + i00 + rs);
        __nv_bfloat162 v11 = *(const __nv_bfloat162*)(base + i00 + rs + 256);
        float m0 = fmaxf(fmaxf(__bfloat162float(v00.x), __bfloat162float(v01.x)),
                         fmaxf(__bfloat162float(v10.x), __bfloat162float(v11.x)));
        float m1 = fmaxf(fmaxf(__bfloat162float(v00.y), __bfloat162float(v01.y)),
                         fmaxf(__bfloat162float(v10.y), __bfloat162float(v11.y)));
        o.x = __float2bfloat16(m0);
        o.y = __float2bfloat16(m1);
    } else {
        o.x = __float2bfloat16(0.f);
        o.y = __float2bfloat16(0.f);
    }
    *(__nv_bfloat162*)(g_act[s] + doff + (e << 1)) = o;
}

// fused global-max feature + linear head
__global__ void k_head(const float* __restrict__ lw, const float* __restrict__ lb,
                       float* __restrict__ out) {
    __shared__ float fs[256];
    int n = blockIdx.y, tid = threadIdx.x;
    const __nv_bfloat16* base = g_act[4] + OFF8;
    float m = -3.4e38f;
    for (int yy = 0; yy < 8; yy++)
        for (int xx = 0; xx < 8; xx++)
            m = fmaxf(m, __bfloat162float(
                base[(((long long)n * 10 + (yy + 1)) * 10 + (xx + 1)) * 256 + tid]));
    fs[tid] = m;
    __syncthreads();
    int cls = blockIdx.x * 256 + tid;
    if (cls < 1000) {
        float a = 0.f;
#pragma unroll 8
        for (int c = 0; c < 256; c++) a += fs[c] * lw[cls * 256 + c];
        out[n * 1000 + cls] = a + lb[cls];
    }
}

// ---------------------------------------------------------------------------
extern "C" void kernel_launch(void* const* d_in, const int* in_sizes, int n_in,
                              void* d_out, int out_size)
{
    const float* x      = (const float*)d_in[0];
    const float* conv_w = (const float*)d_in[1];
    const float* lin_w  = (const float*)d_in[2];
    const float* lin_b  = (const float*)d_in[3];
    const float* alpha  = (const float*)d_in[4];
    const float* gmm    = (const float*)d_in[5];
    const float* bta    = (const float*)d_in[6];
    float* out = (float*)d_out;

    cudaFuncSetAttribute(k_conv, cudaFuncAttributeMaxDynamicSharedMemorySize, 148608);

    k_prep_w<<<576, 256>>>(conv_w);
    k_prep_in<<<139392, 256>>>(x);

    static const int S1[10]  = {0,1,2,3,4,5,0,1,2,3};
    static const int S2[10]  = {0,0,1,2,3,4,5,0,1,2};
    static const int S3[10]  = {0,0,0,1,2,3,4,5,0,1};
    static const int S4[10]  = {0,0,0,0,1,2,3,4,5,0};
    static const int NH[10]  = {1,2,3,4,4,4,4,4,4,4};
    static const int DST[10] = {1,2,3,4,5,0,1,2,3,4};
    static const int HH[10]  = {64,64,64,32,32,32,16,16,16,8};
    static const int LW[10]  = {6,6,6,5,5,5,4,4,4,3};
    static const unsigned long long OFFT[10] =
        {OFF64,OFF64,OFF64,OFF32,OFF32,OFF32,OFF16,OFF16,OFF16,OFF8};

    for (int t = 0; t < 10; t++) {
        int H = HH[t], W = H, P = 32 * H * W;
        unsigned long long off = OFFT[t];
        if (t < 9) {
            int R = 256 / W, W2 = W + 2;
            int dsm = 3 * ((R + 2) * W2 * 32 + 36864);
            dim3 cg(P / 256, 2);
            k_conv<<<cg, 512, dsm>>>(S1[t], S1[t], S2[t], S3[t], S4[t], NH[t],
                                     off, LW[t], alpha, t);
        } else {
            dim3 cg(P / 128, 2);
            k_conv_small<<<cg, 256>>>(S1[t], S1[t], S2[t], S3[t], S4[t], NH[t],
                                      off, LW[t], alpha, t);
        }
        long long tot = (long long)32 * (H + 2) * (W + 2) * 128;
        k_bnq<<<(unsigned)((tot + 255) / 256), 256>>>(DST[t], off, H, W,
                                                      gmm + t * 256, bta + t * 256,
                                                      t, 1.0 / (double)P);
        if (t == 2 || t == 5 || t == 8) {
            int Hd = H / 2, Wd = Hd;
            unsigned long long doff = (t == 2) ? OFF32 : (t == 5) ? OFF16 : OFF8;
            long long pt = (long long)32 * (Hd + 2) * (Wd + 2) * 128;
            int spack = (t == 5) ? (3 | (4 << 8) | (5 << 16) | (0 << 24))
                                 : (0 | (1 << 8) | (2 << 16) | (3 << 24));
            dim3 pg((unsigned)((pt + 255) / 256), 4);
            k_pool4<<<pg, 256>>>(spack, off, doff, Hd, Wd);
        }
    }
    k_head<<<dim3(4, 32), 256>>>(lin_w, lin_b, out);
}

// round 14
// speedup vs baseline: 2.2864x; 1.1733x over previous
#include <cuda_runtime.h>
#include <cuda_bf16.h>
#include <cstdint>

#define SLOT_ELEMS 45154304ull
#define OFF64 0ull
#define OFF32 35684352ull
#define OFF16 0ull
#define OFF8  4000000ull

__device__ __align__(16) __nv_bfloat16 g_act[6][SLOT_ELEMS];
__device__ __align__(16) float         g_scratch[33554432];   // fp32 pre-BN [pixel][256]
__device__ __align__(16) uint2         g_wf[147456];          // [tap][kc][P][lane][which]
__device__ double g_sumA[2560];
__device__ double g_sqA[2560];

__device__ __forceinline__ unsigned su32(const void* p) {
    return (unsigned)__cvta_generic_to_shared(p);
}

#define MMA_(c, a, b)                                                           \
    asm volatile("mma.sync.aligned.m16n8k16.row.col.f32.bf16.bf16.f32 "         \
                 "{%0,%1,%2,%3},{%4,%5,%6,%7},{%8,%9},{%0,%1,%2,%3};\n"         \
                 : "+f"(c[0]), "+f"(c[1]), "+f"(c[2]), "+f"(c[3])               \
                 : "r"(a[0]), "r"(a[1]), "r"(a[2]), "r"(a[3]),                  \
                   "r"(b.x), "r"(b.y))

// conv_w (OIHW fp32, int/64) -> paired-fragment layout:
// uint2 index = ((tap*16+kc)*16+P)*64 + lane*2 + which ; frag for cout-block nb=2P+which
__global__ void k_prep_w(const float* __restrict__ cw) {
    int idx = blockIdx.x * 256 + threadIdx.x;
    if (idx < 2560) { g_sumA[idx] = 0.0; g_sqA[idx] = 0.0; }
    if (idx >= 147456) return;
    int tap = idx >> 14;
    int rem = idx & 16383;
    int kc  = rem >> 10;
    int r2  = rem & 1023;
    int P   = r2 >> 6;
    int l2  = r2 & 63;
    int lane = l2 >> 1, which = l2 & 1;
    int nb = 2 * P + which;
    int g = lane >> 2, qd = lane & 3;
    int co = nb * 8 + g, ci0 = kc * 16 + 2 * qd;
    __nv_bfloat162 lo, hi;
    lo.x = __float2bfloat16(cw[(co * 256 + ci0    ) * 9 + tap]);
    lo.y = __float2bfloat16(cw[(co * 256 + ci0 + 1) * 9 + tap]);
    hi.x = __float2bfloat16(cw[(co * 256 + ci0 + 8) * 9 + tap]);
    hi.y = __float2bfloat16(cw[(co * 256 + ci0 + 9) * 9 + tap]);
    uint2 v;
    v.x = *(unsigned*)&lo;
    v.y = *(unsigned*)&hi;
    g_wf[idx] = v;
}

// zero halo ring of the padded H x W region at `off` for all 6 slots (grid.z)
__global__ void k_zero_halo(unsigned long long off, int H, int W) {
    int s = blockIdx.z;
    int W2 = W + 2, H2 = H + 2;
    int Ph = 2 * W2 + 2 * H;                 // halo pixels per image
    int id = blockIdx.x * 256 + threadIdx.x; // over 32 * Ph * 32 (16B chunks)
    int total = 32 * Ph * 32;
    if (id >= total) return;
    int chunk = id & 31;
    int r = id >> 5;
    int k = r % Ph;
    int n = r / Ph;
    int py, px;
    if (k < W2)            { py = 0;      px = k; }
    else if (k < 2 * W2)   { py = H + 1;  px = k - W2; }
    else { int j = k - 2 * W2; py = 1 + (j >> 1); px = (j & 1) ? (W + 1) : 0; }
    *(uint4*)&g_act[s][off + ((long long)(n * H2 + py) * W2 + px) * 256 + chunk * 8] =
        make_uint4(0, 0, 0, 0);
}

// x (32,3,64,64) fp32 -> quantize (v=64), pad ch->256, interior write only
__global__ void k_prep_in(const float* __restrict__ x) {
    int e = blockIdx.x * 256 + threadIdx.x;  // over 32*64*64*64 (4ch chunks)
    if (e >= 8388608) return;
    int c4 = e & 63;
    int p = e >> 6;
    int px = p & 63, py = (p >> 6) & 63, n = p >> 12;
    unsigned o0 = 0, o1 = 0;
    if (c4 == 0) {
        __nv_bfloat162 a, b;
        float v0 = truncf(x[(((long long)n * 3 + 0) * 64 + py) * 64 + px] * 0.015625f) * 0.015625f;
        float v1 = truncf(x[(((long long)n * 3 + 1) * 64 + py) * 64 + px] * 0.015625f) * 0.015625f;
        float v2 = truncf(x[(((long long)n * 3 + 2) * 64 + py) * 64 + px] * 0.015625f) * 0.015625f;
        a.x = __float2bfloat16(v0); a.y = __float2bfloat16(v1);
        b.x = __float2bfloat16(v2); b.y = __float2bfloat16(0.f);
        o0 = *(unsigned*)&a; o1 = *(unsigned*)&b;
    }
    *(uint2*)&g_act[0][((long long)(n * 66 + py + 1) * 66 + px + 1) * 256 + c4 * 4] =
        make_uint2(o0, o1);
}

// ---------------------------------------------------------------------------
// Big conv (t<9): CTA 512 thr, 16 warps (8M x 2N), warp M32 x N64.
// Tile M256 x N128, K=2304, 16 kc-stages, triple-buffered cp.async.
// ---------------------------------------------------------------------------
__global__ void __launch_bounds__(512, 1) k_conv(
    int sPrev, int s1, int s2, int s3, int s4, int nhist,
    unsigned long long off, int lw,
    const float* __restrict__ alpha, int t)
{
    extern __shared__ __align__(16) char dynsmem[];
    __shared__ float s_sum[128], s_sq[128];

    const int tid = threadIdx.x, warp = tid >> 5, lane = tid & 31;
    const int g = lane >> 2, qd = lane & 3;
    const int mw = warp >> 1, nw = warp & 1;
    const int m_off = mw * 32, n_off = nw * 64;
    const int p0 = blockIdx.x * 256, co0 = blockIdx.y * 128;
    const int W = 1 << lw, W2 = W + 2, R = 256 >> lw;
    const int ASLAB = (R + 2) * W2 * 32;
    const int STAGE = ASLAB + 36864;

    if (tid < 128) { s_sum[tid] = 0.f; s_sq[tid] = 0.f; }

    const int n_img = p0 >> (2 * lw);
    const int y0    = (p0 >> lw) & (W - 1);
    const char* aBase = (const char*)(g_act[sPrev] + off);

    const int nA = (R + 2) * W2 * 2, ntot = nA + 2304;
    const char* csrc[7]; unsigned cdst[7]; int ckst[7]; int cnt = 0;
#pragma unroll
    for (int k = 0; k < 7; k++) {
        int c = tid + k * 512;
        if (c >= ntot) break;
        if (c < nA) {
            int e = c >> 1, h = c & 1;
            int ry = e / W2, cx = e - ry * W2;
            csrc[cnt] = aBase + (long long)((n_img * W2 + y0 + ry) * W2 + cx) * 512 + h * 16;
            cdst[cnt] = (unsigned)(e * 32 + ((h ^ ((cx >> 2) & 1)) << 4));
            ckst[cnt] = 32;
        } else {
            int b = c - nA, tap = b >> 8, rest = b & 255;
            csrc[cnt] = (const char*)g_wf + tap * 131072 + (co0 >> 4) * 512 + rest * 16;
            cdst[cnt] = (unsigned)(ASLAB + tap * 4096 + rest * 16);
            ckst[cnt] = 8192;
        }
        cnt++;
    }
    const unsigned smbase = su32(dynsmem);

#define ISSUE(kc_) {                                                            \
    unsigned sb_ = smbase + ((kc_) % 3) * STAGE;                                \
    for (int i_ = 0; i_ < cnt; i_++)                                            \
        asm volatile("cp.async.cg.shared.global [%0],[%1],16;\n"                \
            :: "r"(sb_ + cdst[i_]), "l"(csrc[i_] + (kc_) * ckst[i_]));          \
    asm volatile("cp.async.commit_group;\n"); }

    int em[2], xm[2];
    const int hh = lane >> 4;
#pragma unroll
    for (int ms = 0; ms < 2; ms++) {
        int pt = m_off + ms * 16 + (lane & 15);
        int ry = pt >> lw, x = pt & (W - 1);
        em[ms] = ry * W2 + x;
        xm[ms] = x;
    }

    float acc[2][8][4];
#pragma unroll
    for (int i = 0; i < 2; i++)
#pragma unroll
        for (int j = 0; j < 8; j++)
#pragma unroll
            for (int k = 0; k < 4; k++) acc[i][j][k] = 0.f;

    ISSUE(0);
    for (int kc = 0; kc < 16; kc++) {
        if (kc < 15) { ISSUE(kc + 1); asm volatile("cp.async.wait_group 1;\n" ::); }
        else         { asm volatile("cp.async.wait_group 0;\n" ::); }
        __syncthreads();

        const unsigned Ac = smbase + (kc % 3) * STAGE;
        const char*    Bc = dynsmem + (kc % 3) * STAGE + ASLAB;

#pragma unroll
        for (int tap = 0; tap < 9; tap++) {
            const int ky = tap / 3, kx = tap - 3 * (tap / 3);
            uint2 bq[8];
            const uint4* bp = (const uint4*)(Bc + tap * 4096 + nw * 2048 + lane * 16);
#pragma unroll
            for (int j = 0; j < 4; j++) {
                uint4 q = bp[j * 32];
                bq[2 * j]     = make_uint2(q.x, q.y);
                bq[2 * j + 1] = make_uint2(q.z, q.w);
            }
            unsigned am[2][4];
#pragma unroll
            for (int ms = 0; ms < 2; ms++) {
                int cx = xm[ms] + kx;
                unsigned ad = Ac + (unsigned)((em[ms] + ky * W2 + kx) * 32)
                                 + (unsigned)((hh ^ ((cx >> 2) & 1)) << 4);
                asm volatile("ldmatrix.sync.aligned.m8n8.x4.shared.b16 {%0,%1,%2,%3},[%4];\n"
                             : "=r"(am[ms][0]), "=r"(am[ms][1]),
                               "=r"(am[ms][2]), "=r"(am[ms][3]) : "r"(ad));
            }
#pragma unroll
            for (int ns = 0; ns < 8; ns++) {
                MMA_(acc[0][ns], am[0], bq[ns]);
                MMA_(acc[1][ns], am[1], bq[ns]);
            }
        }
    }
#undef ISSUE

    const float a0c = alpha[t * 6];
    int slots[4] = { s1, s2, s3, s4 };
    float coef[4] = { 0.f, 0.f, 0.f, 0.f };
    for (int d = 1; d <= nhist; d++) coef[d - 1] = alpha[t * 6 + 6 - d];

    float cs[16], cq[16];
#pragma unroll
    for (int j = 0; j < 16; j++) { cs[j] = 0.f; cq[j] = 0.f; }

#pragma unroll
    for (int ms = 0; ms < 2; ms++) {
#pragma unroll
        for (int half = 0; half < 2; half++) {
            int pe  = p0 + m_off + ms * 16 + g + half * 8;
            int ne  = pe >> (2 * lw);
            int rme = pe & ((1 << (2 * lw)) - 1);
            int ye = rme >> lw, xe = rme & (W - 1);
            long long hb = (long long)off + ((long long)(ne * W2 + ye + 1) * W2 + xe + 1) * 256
                           + co0 + n_off + 2 * qd;
            long long sb2 = (long long)pe * 256 + co0 + n_off + 2 * qd;
#pragma unroll
            for (int ns = 0; ns < 8; ns++) {
                float v0 = a0c * fmaxf(acc[ms][ns][half * 2 + 0], 0.f);
                float v1 = a0c * fmaxf(acc[ms][ns][half * 2 + 1], 0.f);
                for (int d = nhist; d >= 1; d--) {
                    __nv_bfloat162 hv = *(const __nv_bfloat162*)&g_act[slots[d - 1]][hb + ns * 8];
                    v0 += coef[d - 1] * __bfloat162float(hv.x);
                    v1 += coef[d - 1] * __bfloat162float(hv.y);
                }
                *(float2*)&g_scratch[sb2 + ns * 8] = make_float2(v0, v1);
                cs[ns * 2 + 0] += v0;      cs[ns * 2 + 1] += v1;
                cq[ns * 2 + 0] += v0 * v0; cq[ns * 2 + 1] += v1 * v1;
            }
        }
    }
#pragma unroll
    for (int m = 4; m < 32; m <<= 1) {
#pragma unroll
        for (int j = 0; j < 16; j++) {
            cs[j] += __shfl_xor_sync(0xffffffffu, cs[j], m);
            cq[j] += __shfl_xor_sync(0xffffffffu, cq[j], m);
        }
    }
    if (lane < 4) {
#pragma unroll
        for (int ns = 0; ns < 8; ns++) {
            int ch = n_off + ns * 8 + 2 * lane;
            atomicAdd(&s_sum[ch],     cs[ns * 2 + 0]);
            atomicAdd(&s_sum[ch + 1], cs[ns * 2 + 1]);
            atomicAdd(&s_sq[ch],      cq[ns * 2 + 0]);
            atomicAdd(&s_sq[ch + 1],  cq[ns * 2 + 1]);
        }
    }
    __syncthreads();
    if (tid < 128) {
        atomicAdd(&g_sumA[t * 256 + co0 + tid], (double)s_sum[tid]);
        atomicAdd(&g_sqA [t * 256 + co0 + tid], (double)s_sq[tid]);
    }
}

// ---------------------------------------------------------------------------
// Small conv (res8): tap-major, CTA 256 thr, M128 x N128, 144 stages.
// ---------------------------------------------------------------------------
__global__ void __launch_bounds__(256, 2) k_conv_small(
    int sPrev, int s1, int s2, int s3, int s4, int nhist,
    unsigned long long off, int lw,
    const float* __restrict__ alpha, int t)
{
    constexpr int S   = 144;
    constexpr int STB = 4096;
    __shared__ __align__(256) char As[3 * STB];
    __shared__ float s_sum[128], s_sq[128];

    const int tid = threadIdx.x, warp = tid >> 5, lane = tid & 31;
    const int g = lane >> 2, qd = lane & 3;
    const int mw = warp >> 1, nw = warp & 1;
    const int m_off = mw * 32, n_off = nw * 64;
    const int p0 = blockIdx.x * 128, co0 = blockIdx.y * 128;
    const int W = 1 << lw, W2 = W + 2;

    if (tid < 128) { s_sum[tid] = 0.f; s_sq[tid] = 0.f; }

    const int r = tid >> 1, h = tid & 1;
    int p  = p0 + r;
    int n  = p >> (2 * lw);
    int rm = p & ((1 << (2 * lw)) - 1);
    int yy = rm >> lw, xx = rm & (W - 1);
    const __nv_bfloat16* hp = g_act[sPrev] + off;
    const char* rowp[3];
#pragma unroll
    for (int ky = 0; ky < 3; ky++)
        rowp[ky] = (const char*)(hp + ((long long)(n * W2 + yy + ky) * W2 + xx) * 256 + h * 8);

    const int rr = r & 7;
    const unsigned dstb = su32(As) + (r >> 3) * 256 + ((rr * 2 + (h ^ ((rr >> 2) & 1))) << 4);
    const int rl = m_off + (lane & 15), hh = lane >> 4, rlr = rl & 7;
    const unsigned ldsb = su32(As) + (rl >> 3) * 256 + ((rlr * 2 + (hh ^ ((rlr >> 2) & 1))) << 4);

#define CPA(s_, ph_) {                                                          \
    int tap_ = (s_) >> 4, kc_ = (s_) & 15;                                      \
    int ky_ = (tap_ * 11) >> 5; int kx_ = tap_ - 3 * ky_;                       \
    const char* src_ = rowp[ky_] + kx_ * 512 + kc_ * 32;                        \
    asm volatile("cp.async.cg.shared.global [%0],[%1],16;\n"                    \
                 :: "r"(dstb + (ph_) * STB), "l"(src_));                        \
    asm volatile("cp.async.commit_group;\n"); }

#define LDB(dst) {                                                              \
    uint4 q0 = wptr[0], q1 = wptr[32], q2 = wptr[64], q3 = wptr[96];            \
    dst[0] = make_uint2(q0.x, q0.y); dst[1] = make_uint2(q0.z, q0.w);           \
    dst[2] = make_uint2(q1.x, q1.y); dst[3] = make_uint2(q1.z, q1.w);           \
    dst[4] = make_uint2(q2.x, q2.y); dst[5] = make_uint2(q2.z, q2.w);           \
    dst[6] = make_uint2(q3.x, q3.y); dst[7] = make_uint2(q3.z, q3.w);           \
    wptr += 512; }

    float acc[2][8][4];
#pragma unroll
    for (int i = 0; i < 2; i++)
#pragma unroll
        for (int j = 0; j < 8; j++)
#pragma unroll
            for (int k = 0; k < 4; k++) acc[i][j][k] = 0.f;

    uint2 bA[8], bB[8];
    const uint4* wptr = (const uint4*)((const char*)g_wf + (co0 >> 4) * 512 + nw * 2048 + lane * 16);
    LDB(bA);
    CPA(0, 0); CPA(1, 1);

#define BODY(j_, CUR, NXT) {                                                    \
    int s_ = sb + (j_);                                                         \
    if (s_ == S - 1) asm volatile("cp.async.wait_group 0;\n" ::);               \
    else             asm volatile("cp.async.wait_group 1;\n" ::);               \
    __syncthreads();                                                            \
    if (s_ + 2 < S) CPA(s_ + 2, ((j_) + 2) % 3);                                \
    if (s_ + 1 < S) LDB(NXT);                                                   \
    unsigned a0[4], a1[4];                                                      \
    unsigned base_ = ldsb + ((j_) % 3) * STB;                                   \
    asm volatile("ldmatrix.sync.aligned.m8n8.x4.shared.b16 {%0,%1,%2,%3},[%4];\n" \
                 : "=r"(a0[0]), "=r"(a0[1]), "=r"(a0[2]), "=r"(a0[3]) : "r"(base_)); \
    asm volatile("ldmatrix.sync.aligned.m8n8.x4.shared.b16 {%0,%1,%2,%3},[%4];\n" \
                 : "=r"(a1[0]), "=r"(a1[1]), "=r"(a1[2]), "=r"(a1[3]) : "r"(base_ + 512)); \
    _Pragma("unroll")                                                           \
    for (int ns = 0; ns < 8; ns++) {                                            \
        MMA_(acc[0][ns], a0, CUR[ns]);                                          \
        MMA_(acc[1][ns], a1, CUR[ns]);                                          \
    } }

    for (int sb = 0; sb < S; sb += 6) {
        BODY(0, bA, bB); BODY(1, bB, bA); BODY(2, bA, bB);
        BODY(3, bB, bA); BODY(4, bA, bB); BODY(5, bB, bA);
    }
#undef BODY
#undef CPA
#undef LDB

    const float a0c = alpha[t * 6];
    int slots[4] = { s1, s2, s3, s4 };
    float coef[4] = { 0.f, 0.f, 0.f, 0.f };
    for (int d = 1; d <= nhist; d++) coef[d - 1] = alpha[t * 6 + 6 - d];

    float cs[16], cq[16];
#pragma unroll
    for (int j = 0; j < 16; j++) { cs[j] = 0.f; cq[j] = 0.f; }

#pragma unroll
    for (int ms = 0; ms < 2; ms++) {
#pragma unroll
        for (int half = 0; half < 2; half++) {
            int pe  = p0 + m_off + ms * 16 + g + half * 8;
            int ne  = pe >> (2 * lw);
            int rme = pe & ((1 << (2 * lw)) - 1);
            int ye = rme >> lw, xe = rme & (W - 1);
            long long hb = (long long)off + ((long long)(ne * W2 + ye + 1) * W2 + xe + 1) * 256
                           + co0 + n_off + 2 * qd;
            long long sb2 = (long long)pe * 256 + co0 + n_off + 2 * qd;
#pragma unroll
            for (int ns = 0; ns < 8; ns++) {
                float v0 = a0c * fmaxf(acc[ms][ns][half * 2 + 0], 0.f);
                float v1 = a0c * fmaxf(acc[ms][ns][half * 2 + 1], 0.f);
                for (int d = nhist; d >= 1; d--) {
                    __nv_bfloat162 hv = *(const __nv_bfloat162*)&g_act[slots[d - 1]][hb + ns * 8];
                    v0 += coef[d - 1] * __bfloat162float(hv.x);
                    v1 += coef[d - 1] * __bfloat162float(hv.y);
                }
                *(float2*)&g_scratch[sb2 + ns * 8] = make_float2(v0, v1);
                cs[ns * 2 + 0] += v0;      cs[ns * 2 + 1] += v1;
                cq[ns * 2 + 0] += v0 * v0; cq[ns * 2 + 1] += v1 * v1;
            }
        }
    }
#pragma unroll
    for (int m = 4; m < 32; m <<= 1) {
#pragma unroll
        for (int j = 0; j < 16; j++) {
            cs[j] += __shfl_xor_sync(0xffffffffu, cs[j], m);
            cq[j] += __shfl_xor_sync(0xffffffffu, cq[j], m);
        }
    }
    if (lane < 4) {
#pragma unroll
        for (int ns = 0; ns < 8; ns++) {
            int ch = n_off + ns * 8 + 2 * lane;
            atomicAdd(&s_sum[ch],     cs[ns * 2 + 0]);
            atomicAdd(&s_sum[ch + 1], cs[ns * 2 + 1]);
            atomicAdd(&s_sq[ch],      cq[ns * 2 + 0]);
            atomicAdd(&s_sq[ch + 1],  cq[ns * 2 + 1]);
        }
    }
    __syncthreads();
    if (tid < 128) {
        atomicAdd(&g_sumA[t * 256 + co0 + tid], (double)s_sum[tid]);
        atomicAdd(&g_sqA [t * 256 + co0 + tid], (double)s_sq[tid]);
    }
}

// BN (stats inline) + trunc-quantize, interior-only, 4 ch/thread
__global__ void k_bnq(int sd, unsigned long long doff, int lw,
                      const float* __restrict__ gamma, const float* __restrict__ beta,
                      int t, double invP)
{
    __shared__ float smu[256], srstd[256];
    int tid = threadIdx.x;
    if (tid < 128) {
#pragma unroll
        for (int j = 0; j < 2; j++) {
            int c = 2 * tid + j;
            double mu  = g_sumA[t * 256 + c] * invP;
            double var = g_sqA[t * 256 + c] * invP - mu * mu;
            smu[c]   = (float)mu;
            srstd[c] = rsqrtf((float)var + 1e-5f);
        }
    }
    __syncthreads();
    int W = 1 << lw, W2 = W + 2;
    long long total = (long long)32 << (2 * lw + 6);  // 32*H*W*64
    long long e = (long long)blockIdx.x * 256 + tid;
    if (e >= total) return;
    int c4 = (int)(e & 63);
    long long p = e >> 6;
    int px = (int)(p & (W - 1));
    int py = (int)((p >> lw) & (W - 1));
    int n  = (int)(p >> (2 * lw));
    int c = c4 * 4;
    const float4 v = *(const float4*)&g_scratch[(p << 8) + c];
    float b0 = gamma[c]     * ((v.x - smu[c])     * srstd[c])     + beta[c];
    float b1 = gamma[c + 1] * ((v.y - smu[c + 1]) * srstd[c + 1]) + beta[c + 1];
    float b2 = gamma[c + 2] * ((v.z - smu[c + 2]) * srstd[c + 2]) + beta[c + 2];
    float b3 = gamma[c + 3] * ((v.w - smu[c + 3]) * srstd[c + 3]) + beta[c + 3];
    __nv_bfloat162 o0, o1;
    o0.x = __float2bfloat16(truncf(b0 * 0.015625f) * 0.015625f);
    o0.y = __float2bfloat16(truncf(b1 * 0.015625f) * 0.015625f);
    o1.x = __float2bfloat16(truncf(b2 * 0.015625f) * 0.015625f);
    o1.y = __float2bfloat16(truncf(b3 * 0.015625f) * 0.015625f);
    *(uint2*)&g_act[sd][doff + ((long long)(n * W2 + py + 1) * W2 + px + 1) * 256 + c] =
        make_uint2(*(unsigned*)&o0, *(unsigned*)&o1);
}

// 2x2 maxpool, interior-only, 4 slots via grid.y, dst res H=W=2^lw
__global__ void k_pool4(int spack, unsigned long long soff, unsigned long long doff,
                        int lw)
{
    int s = (spack >> (blockIdx.y * 8)) & 0xff;
    int W = 1 << lw, W2 = W + 2, SW2 = 2 * W + 2;
    long long total = (long long)32 << (2 * lw + 7);  // 32*H*W*128
    long long e = (long long)blockIdx.x * 256 + threadIdx.x;
    if (e >= total) return;
    int cp = (int)(e & 127);
    long long p = e >> 7;
    int px = (int)(p & (W - 1));
    int py = (int)((p >> lw) & (W - 1));
    int n  = (int)(p >> (2 * lw));
    const __nv_bfloat16* base = g_act[s] + soff;
    long long i00 = (((long long)n * (2 * W + 2) + (2 * py + 1)) * SW2 + (2 * px + 1)) * 256 + cp * 2;
    long long rs = (long long)SW2 * 256;
    __nv_bfloat162 v00 = *(const __nv_bfloat162*)(base + i00);
    __nv_bfloat162 v01 = *(const __nv_bfloat162*)(base + i00 + 256);
    __nv_bfloat162 v10 = *(const __nv_bfloat162*)(base + i00 + rs);
    __nv_bfloat162 v11 = *(const __nv_bfloat162*)(base + i00 + rs + 256);
    __nv_bfloat162 o;
    o.x = __float2bfloat16(fmaxf(fmaxf(__bfloat162float(v00.x), __bfloat162float(v01.x)),
                                 fmaxf(__bfloat162float(v10.x), __bfloat162float(v11.x))));
    o.y = __float2bfloat16(fmaxf(fmaxf(__bfloat162float(v00.y), __bfloat162float(v01.y)),
                                 fmaxf(__bfloat162float(v10.y), __bfloat162float(v11.y))));
    *(__nv_bfloat162*)(g_act[s] + doff +
        ((long long)(n * W2 + py + 1) * W2 + px + 1) * 256 + cp * 2) = o;
}

// fused global-max feature + linear head
__global__ void k_head(const float* __restrict__ lw, const float* __restrict__ lb,
                       float* __restrict__ out) {
    __shared__ float fs[256];
    int n = blockIdx.y, tid = threadIdx.x;
    const __nv_bfloat16* base = g_act[4] + OFF8;
    float m = -3.4e38f;
    for (int yy = 0; yy < 8; yy++)
        for (int xx = 0; xx < 8; xx++)
            m = fmaxf(m, __bfloat162float(
                base[(((long long)n * 10 + (yy + 1)) * 10 + (xx + 1)) * 256 + tid]));
    fs[tid] = m;
    __syncthreads();
    int cls = blockIdx.x * 256 + tid;
    if (cls < 1000) {
        float a = 0.f;
#pragma unroll 8
        for (int c = 0; c < 256; c++) a += fs[c] * lw[cls * 256 + c];
        out[n * 1000 + cls] = a + lb[cls];
    }
}

// ---------------------------------------------------------------------------
extern "C" void kernel_launch(void* const* d_in, const int* in_sizes, int n_in,
                              void* d_out, int out_size)
{
    const float* x      = (const float*)d_in[0];
    const float* conv_w = (const float*)d_in[1];
    const float* lin_w  = (const float*)d_in[2];
    const float* lin_b  = (const float*)d_in[3];
    const float* alpha  = (const float*)d_in[4];
    const float* gmm    = (const float*)d_in[5];
    const float* bta    = (const float*)d_in[6];
    float* out = (float*)d_out;

    cudaFuncSetAttribute(k_conv, cudaFuncAttributeMaxDynamicSharedMemorySize, 148608);

    k_prep_w<<<576, 256>>>(conv_w);
    // zero halos for all 6 slots at all 4 resolutions
    {
        static const int HZ[4] = {64, 32, 16, 8};
        static const unsigned long long OZ[4] = {OFF64, OFF32, OFF16, OFF8};
        for (int i = 0; i < 4; i++) {
            int H = HZ[i], Ph = 2 * (H + 2) + 2 * H;
            int tot = 32 * Ph * 32;
            dim3 zg((tot + 255) / 256, 1, 6);
            k_zero_halo<<<zg, 256>>>(OZ[i], H, H);
        }
    }
    k_prep_in<<<32768, 256>>>(x);

    static const int S1[10]  = {0,1,2,3,4,5,0,1,2,3};
    static const int S2[10]  = {0,0,1,2,3,4,5,0,1,2};
    static const int S3[10]  = {0,0,0,1,2,3,4,5,0,1};
    static const int S4[10]  = {0,0,0,0,1,2,3,4,5,0};
    static const int NH[10]  = {1,2,3,4,4,4,4,4,4,4};
    static const int DST[10] = {1,2,3,4,5,0,1,2,3,4};
    static const int HH[10]  = {64,64,64,32,32,32,16,16,16,8};
    static const int LW[10]  = {6,6,6,5,5,5,4,4,4,3};
    static const unsigned long long OFFT[10] =
        {OFF64,OFF64,OFF64,OFF32,OFF32,OFF32,OFF16,OFF16,OFF16,OFF8};

    for (int t = 0; t < 10; t++) {
        int H = HH[t], W = H, P = 32 * H * W;
        unsigned long long off = OFFT[t];
        if (t < 9) {
            int R = 256 / W, W2 = W + 2;
            int dsm = 3 * ((R + 2) * W2 * 32 + 36864);
            dim3 cg(P / 256, 2);
            k_conv<<<cg, 512, dsm>>>(S1[t], S1[t], S2[t], S3[t], S4[t], NH[t],
                                     off, LW[t], alpha, t);
        } else {
            dim3 cg(P / 128, 2);
            k_conv_small<<<cg, 256>>>(S1[t], S1[t], S2[t], S3[t], S4[t], NH[t],
                                      off, LW[t], alpha, t);
        }
        long long tot = (long long)P * 64;
        k_bnq<<<(unsigned)((tot + 255) / 256), 256>>>(DST[t], off, LW[t],
                                                      gmm + t * 256, bta + t * 256,
                                                      t, 1.0 / (double)P);
        if (t == 2 || t == 5 || t == 8) {
            int lwd = LW[t] - 1;
            unsigned long long doff = (t == 2) ? OFF32 : (t == 5) ? OFF16 : OFF8;
            long long pt = (long long)32 << (2 * lwd + 7);
            int spack = (t == 5) ? (3 | (4 << 8) | (5 << 16) | (0 << 24))
                                 : (0 | (1 << 8) | (2 << 16) | (3 << 24));
            dim3 pg((unsigned)((pt + 255) / 256), 4);
            k_pool4<<<pg, 256>>>(spack, off, doff, lwd);
        }
    }
    k_head<<<dim3(4, 32), 256>>>(lin_w, lin_b, out);
}